// round 13
// baseline (speedup 1.0000x reference)
#include <cuda_runtime.h>
#include <cuda_fp16.h>
#include <cstdint>

#define B_  2
#define T_  2048
#define S_  2048
#define HID 1024
#define NH  16
#define DH  64
#define M_  (B_ * T_)   // 4096

// Scratch (static device globals — no allocation APIs)
__device__ __half g_t16[M_ * HID];
__device__ __half g_s16[M_ * HID];
__device__ __half g_wq[HID * HID];
__device__ __half g_wk[HID * HID];
__device__ __half g_wv[HID * HID];
__device__ __half g_wo[HID * HID];
__device__ __half g_q[M_ * HID];
__device__ __half g_k[M_ * HID];
__device__ __half g_v[M_ * HID];
__device__ __half g_h[M_ * HID];

// ---------------------------------------------------------------------------
// helpers
// ---------------------------------------------------------------------------
__device__ __forceinline__ uint32_t pk16(float x, float y) {
    uint32_t r;   // low half = x, high half = y
    asm("cvt.rn.f16x2.f32 %0, %1, %2;" : "=r"(r) : "f"(y), "f"(x));
    return r;
}
__device__ __forceinline__ uint32_t ex2h2(uint32_t x) {
    uint32_t r;   // 2^x on both fp16 halves, one MUFU op
    asm("ex2.approx.f16x2 %0, %1;" : "=r"(r) : "r"(x));
    return r;
}
__device__ __forceinline__ void mma_f16(float* c, const uint32_t* a,
                                        uint32_t b0, uint32_t b1) {
    asm volatile(
        "mma.sync.aligned.m16n8k16.row.col.f32.f16.f16.f32 "
        "{%0,%1,%2,%3}, {%4,%5,%6,%7}, {%8,%9}, {%0,%1,%2,%3};"
        : "+f"(c[0]), "+f"(c[1]), "+f"(c[2]), "+f"(c[3])
        : "r"(a[0]), "r"(a[1]), "r"(a[2]), "r"(a[3]), "r"(b0), "r"(b1));
}
__device__ __forceinline__ uint32_t smem_u32(const void* p) {
    uint32_t a;
    asm("{ .reg .u64 t; cvta.to.shared.u64 t, %1; cvt.u32.u64 %0, t; }"
        : "=r"(a) : "l"(p));
    return a;
}
#define LDSM4(r, a) \
    asm volatile("ldmatrix.sync.aligned.m8n8.x4.shared.b16 {%0,%1,%2,%3}, [%4];" \
        : "=r"((r)[0]), "=r"((r)[1]), "=r"((r)[2]), "=r"((r)[3]) : "r"(a))
#define LDSM4T(r, a) \
    asm volatile("ldmatrix.sync.aligned.m8n8.x4.trans.shared.b16 {%0,%1,%2,%3}, [%4];" \
        : "=r"((r)[0]), "=r"((r)[1]), "=r"((r)[2]), "=r"((r)[3]) : "r"(a))
#define CPA16(dst, src) \
    asm volatile("cp.async.cg.shared.global [%0], [%1], 16;" :: "r"(dst), "l"(src))
#define CPA_COMMIT() asm volatile("cp.async.commit_group;" ::: "memory")
#define CPA_WAIT1()  asm volatile("cp.async.wait_group 1;" ::: "memory")

// ---------------------------------------------------------------------------
// fused f32 -> f16 for all six tensors (one launch)
// ---------------------------------------------------------------------------
__global__ __launch_bounds__(256) void f2h_all(
    const float* __restrict__ tgt, const float* __restrict__ src,
    const float* __restrict__ Wq, const float* __restrict__ Wk,
    const float* __restrict__ Wv, const float* __restrict__ Wo,
    __half* t16, __half* s16, __half* wq, __half* wk, __half* wv, __half* wo)
{
    const int bid = blockIdx.x;
    const float* s;
    __half* d;
    int base;
    if      (bid < 4096)  { s = tgt; d = t16; base = bid; }
    else if (bid < 8192)  { s = src; d = s16; base = bid - 4096; }
    else if (bid < 9216)  { s = Wq;  d = wq;  base = bid - 8192; }
    else if (bid < 10240) { s = Wk;  d = wk;  base = bid - 9216; }
    else if (bid < 11264) { s = Wv;  d = wv;  base = bid - 10240; }
    else                  { s = Wo;  d = wo;  base = bid - 11264; }
    const int i = base * 256 + threadIdx.x;
    float4 v = ((const float4*)s)[i];
    ((uint2*)d)[i] = make_uint2(pk16(v.x, v.y), pk16(v.z, v.w));
}

// ---------------------------------------------------------------------------
// fp16 GEMM core v2: 256x128 CTA tile, 8 warps as 4(m) x 2(n), each warp
// owns a 64x64 tile — per ks: 4 A-LDSM + 4 B-LDSM feed 32 MMAs (128 B/MMA
// of smem traffic vs 192 before). k-chunk 64, 3-stage cp.async, 1 CTA/SM.
// ---------------------------------------------------------------------------
#define PA2 36
#define PB  68
#define GSMEM ((3 * 256 * PA2 + 3 * 64 * PB) * 4)   // 162816 B

__device__ __forceinline__ void gemm_core(
    const __half* __restrict__ A, const __half* __restrict__ W,
    const float* __restrict__ bias, void* __restrict__ Cout,
    int headMode, int halfOut, uint32_t* sm)
{
    uint32_t* sA = sm;                  // 3 * 256 * PA2
    uint32_t* sB = sm + 3 * 256 * PA2;  // 3 * 64 * PB

    const int tid = threadIdx.x;
    const int lane = tid & 31, wid = tid >> 5;
    const int g = lane >> 2, tq = lane & 3;
    const int wm = wid & 3, wn = wid >> 2;      // 4 x 2 warp grid
    const int m0 = blockIdx.y * 256, n0 = blockIdx.x * 128;

    const uint32_t sAu = smem_u32(sA), sBu = smem_u32(sB);
    const uint32_t aRow = (uint32_t)(wm * 64 + (lane & 15));
    const uint32_t aCol = (uint32_t)((lane >> 4) * 4);
    const uint32_t bRow = (uint32_t)((lane & 7) + (lane & 8));
    const uint32_t bCol = (uint32_t)(wn * 32 + (lane >> 4) * 4);   // wn*64 cols

    float acc[4][8][4];
#pragma unroll
    for (int i = 0; i < 4; i++)
#pragma unroll
        for (int j = 0; j < 8; j++)
#pragma unroll
            for (int u = 0; u < 4; u++) acc[i][j][u] = 0.0f;

    auto issue = [&](int c) {
        const int buf = c % 3;
#pragma unroll
        for (int i = 0; i < 8; ++i) {   // A: 256 rows x 8 chunks of 8 halfs
            const int idx = i * 256 + tid;
            const int row = idx >> 3, j = idx & 7;
            const uint32_t d = sAu + 4 * ((uint32_t)(buf * 256 + row) * PA2 + j * 4);
            CPA16(d, A + (size_t)(m0 + row) * HID + c * 64 + j * 8);
        }
#pragma unroll
        for (int i = 0; i < 4; ++i) {   // B: 64 k-rows x 16 chunks of 8 halfs
            const int idx = i * 256 + tid;
            const int k = idx >> 4, j = idx & 15;
            const int kg = c * 64 + k;
            const __half* src;
            if (headMode) {
                const int n = n0 + j * 8;
                src = W + (size_t)(n >> 6) * (HID * DH) + (size_t)kg * DH + (n & 63);
            } else {
                src = W + (size_t)kg * HID + n0 + j * 8;
            }
            const uint32_t d = sBu + 4 * ((uint32_t)(buf * 64 + k) * PB + j * 4);
            CPA16(d, src);
        }
        CPA_COMMIT();
    };

    issue(0);
    issue(1);

    for (int c = 0; c < 16; ++c) {
        CPA_WAIT1();
        __syncthreads();
        if (c + 2 < 16) issue(c + 2); else CPA_COMMIT();

        const int cur = c % 3;
        const uint32_t aBase = sAu + 4 * ((uint32_t)cur * 256 * PA2);
        const uint32_t bBase = sBu + 4 * ((uint32_t)cur * 64 * PB);
#pragma unroll
        for (int ks = 0; ks < 4; ++ks) {
            uint32_t af[4][4], bf[4][4];
#pragma unroll
            for (int mt = 0; mt < 4; ++mt)
                LDSM4(af[mt], aBase + 4 * ((aRow + mt * 16) * PA2 + aCol + ks * 8));
#pragma unroll
            for (int np = 0; np < 4; ++np)
                LDSM4T(bf[np], bBase + 4 * ((bRow + ks * 16) * PB + bCol + np * 8));
#pragma unroll
            for (int mt = 0; mt < 4; ++mt)
#pragma unroll
                for (int nt = 0; nt < 8; ++nt)
                    mma_f16(acc[mt][nt], af[mt], bf[nt >> 1][(nt & 1) * 2],
                            bf[nt >> 1][(nt & 1) * 2 + 1]);
        }
    }

#pragma unroll
    for (int mt = 0; mt < 4; ++mt) {
        const int r0 = m0 + wm * 64 + mt * 16 + g;
#pragma unroll
        for (int nt = 0; nt < 8; ++nt) {
            const int cl = n0 + wn * 64 + nt * 8 + tq * 2;
            const float b0v = bias[cl], b1v = bias[cl + 1];
            if (halfOut) {
                *(uint32_t*)((__half*)Cout + (size_t)r0 * HID + cl) =
                    pk16(acc[mt][nt][0] + b0v, acc[mt][nt][1] + b1v);
                *(uint32_t*)((__half*)Cout + (size_t)(r0 + 8) * HID + cl) =
                    pk16(acc[mt][nt][2] + b0v, acc[mt][nt][3] + b1v);
            } else {
                *(float2*)((float*)Cout + (size_t)r0 * HID + cl) =
                    make_float2(acc[mt][nt][0] + b0v, acc[mt][nt][1] + b1v);
                *(float2*)((float*)Cout + (size_t)(r0 + 8) * HID + cl) =
                    make_float2(acc[mt][nt][2] + b0v, acc[mt][nt][3] + b1v);
            }
        }
    }
}

__global__ __launch_bounds__(256, 1) void gemm_qkv(
    const __half* __restrict__ t16, const __half* __restrict__ s16,
    const __half* __restrict__ wq, const __half* __restrict__ wk,
    const __half* __restrict__ wv,
    const float* __restrict__ bq, const float* __restrict__ bk,
    const float* __restrict__ bv,
    __half* __restrict__ q, __half* __restrict__ k, __half* __restrict__ v)
{
    extern __shared__ __align__(16) uint32_t sm[];
    const __half* A;
    const __half* W;
    const float* bias;
    __half* C;
    if (blockIdx.z == 0)      { A = t16; W = wq; bias = bq; C = q; }
    else if (blockIdx.z == 1) { A = s16; W = wk; bias = bk; C = k; }
    else                      { A = s16; W = wv; bias = bv; C = v; }
    gemm_core(A, W, bias, C, 1, 1, sm);
}

__global__ __launch_bounds__(256, 1) void gemm_o(
    const __half* __restrict__ A, const __half* __restrict__ W,
    const float* __restrict__ bias, float* __restrict__ C)
{
    extern __shared__ __align__(16) uint32_t sm[];
    gemm_core(A, W, bias, C, 0, 0, sm);
}

// ---------------------------------------------------------------------------
// fp16 flash attention (unchanged from R12): 4 warps x 32 T-rows, no online
// max, f16x2 exp, tensor-pipe row sums via V ones-column.
// ---------------------------------------------------------------------------
#define KP 36
#define ASMEM ((2 * 3 * 64 * KP + 4) * 4)   // 55312 B

__global__ __launch_bounds__(128, 3) void attn_fp16(
    const __half* __restrict__ Q, const __half* __restrict__ K,
    const __half* __restrict__ V, __half* __restrict__ O)
{
    extern __shared__ __align__(16) uint32_t smA[];
    uint32_t* sK = smA;
    uint32_t* sV = smA + 3 * 64 * KP;

    const int tid = threadIdx.x;
    const int lane = tid & 31, wid = tid >> 5;   // wid 0..3
    const int g = lane >> 2, tq = lane & 3;
    const int tb = wid * 32;                      // 32 rows per warp
    const int bh = blockIdx.y, b = bh >> 4, h = bh & 15;
    const int t0 = blockIdx.x * 128;

    const __half* Qb = Q + (size_t)b * T_ * HID + h * DH;
    const __half* Kb = K + (size_t)b * S_ * HID + h * DH;
    const __half* Vb = V + (size_t)b * S_ * HID + h * DH;

    const uint32_t sKu = smem_u32(sK), sVu = smem_u32(sV);
    const uint32_t kRow = (uint32_t)((lane & 7) + ((lane & 16) >> 1));
    const uint32_t kCol = (uint32_t)(((lane >> 3) & 1) * 4);
    const uint32_t vRow = (uint32_t)((lane & 7) + (lane & 8));
    const uint32_t vCol = (uint32_t)((lane >> 4) * 4);

    // ones-column init (V pad col 64 = 1.0, 65..71 = 0) for all 3 buffers
    for (int r = tid; r < 3 * 64; r += 128) {
        sV[r * KP + 32] = 0x00003C00u;
        sV[r * KP + 33] = 0u;
        sV[r * KP + 34] = 0u;
        sV[r * KP + 35] = 0u;
    }

    // Q fragments for both m-tiles, pre-scaled by (1/8)*log2(e)
    const float QSC = 0.125f * 1.44269504f;
    uint32_t qh[4][8];   // [ks][mtile0: 0..3, mtile1: 4..7]
#pragma unroll
    for (int ks = 0; ks < 4; ++ks) {
        const int k = ks * 16 + tq * 2;
#pragma unroll
        for (int mt = 0; mt < 2; ++mt) {
            const size_t r0 = (size_t)(t0 + tb + mt * 16 + g) * HID;
            const size_t r1 = (size_t)(t0 + tb + mt * 16 + g + 8) * HID;
            const uint32_t u0 = *(const uint32_t*)(Qb + r0 + k);
            const uint32_t u1 = *(const uint32_t*)(Qb + r1 + k);
            const uint32_t u2 = *(const uint32_t*)(Qb + r0 + k + 8);
            const uint32_t u3 = *(const uint32_t*)(Qb + r1 + k + 8);
            float2 f0 = __half22float2(*(const __half2*)&u0);
            float2 f1 = __half22float2(*(const __half2*)&u1);
            float2 f2 = __half22float2(*(const __half2*)&u2);
            float2 f3 = __half22float2(*(const __half2*)&u3);
            qh[ks][mt * 4 + 0] = pk16(f0.x * QSC, f0.y * QSC);
            qh[ks][mt * 4 + 1] = pk16(f1.x * QSC, f1.y * QSC);
            qh[ks][mt * 4 + 2] = pk16(f2.x * QSC, f2.y * QSC);
            qh[ks][mt * 4 + 3] = pk16(f3.x * QSC, f3.y * QSC);
        }
    }

    auto issue = [&](int c) {
        const int buf = c % 3;
#pragma unroll
        for (int i = 0; i < 4; ++i) {
            const int idx = i * 128 + tid;
            const int row = idx >> 3, j = idx & 7;
            const uint32_t off = 4 * ((uint32_t)(buf * 64 + row) * KP + j * 4);
            CPA16(sKu + off, Kb + (size_t)(c * 64 + row) * HID + j * 8);
            CPA16(sVu + off, Vb + (size_t)(c * 64 + row) * HID + j * 8);
        }
        CPA_COMMIT();
    };

    float oacc0[8][4], oacc1[8][4];
#pragma unroll
    for (int dt = 0; dt < 8; ++dt)
#pragma unroll
        for (int u = 0; u < 4; ++u) { oacc0[dt][u] = 0.0f; oacc1[dt][u] = 0.0f; }
    float lacc0[4] = {0.f, 0.f, 0.f, 0.f};
    float lacc1[4] = {0.f, 0.f, 0.f, 0.f};

    issue(0);
    issue(1);

    const int NC = S_ / 64;   // 32
    for (int c = 0; c < NC; ++c) {
        CPA_WAIT1();
        __syncthreads();
        if (c + 2 < NC) issue(c + 2); else CPA_COMMIT();

        const int cur = c % 3;
        const uint32_t kBase = sKu + 4 * ((uint32_t)cur * 64 * KP);
        const uint32_t vBase = sVu + 4 * ((uint32_t)cur * 64 * KP);

#pragma unroll
        for (int grp = 0; grp < 4; ++grp) {
            float s0a[4] = {0.f, 0.f, 0.f, 0.f};
            float s0b[4] = {0.f, 0.f, 0.f, 0.f};
            float s1a[4] = {0.f, 0.f, 0.f, 0.f};
            float s1b[4] = {0.f, 0.f, 0.f, 0.f};
#pragma unroll
            for (int ks = 0; ks < 4; ++ks) {
                uint32_t kb[4];
                LDSM4(kb, kBase + 4 * ((kRow + grp * 16) * KP + kCol + ks * 8));
                mma_f16(s0a, &qh[ks][0], kb[0], kb[1]);
                mma_f16(s0b, &qh[ks][0], kb[2], kb[3]);
                mma_f16(s1a, &qh[ks][4], kb[0], kb[1]);
                mma_f16(s1b, &qh[ks][4], kb[2], kb[3]);
            }
            uint32_t a0[4], a1[4];
            a0[0] = ex2h2(pk16(s0a[0], s0a[1]));
            a0[1] = ex2h2(pk16(s0a[2], s0a[3]));
            a0[2] = ex2h2(pk16(s0b[0], s0b[1]));
            a0[3] = ex2h2(pk16(s0b[2], s0b[3]));
            a1[0] = ex2h2(pk16(s1a[0], s1a[1]));
            a1[1] = ex2h2(pk16(s1a[2], s1a[3]));
            a1[2] = ex2h2(pk16(s1b[0], s1b[1]));
            a1[3] = ex2h2(pk16(s1b[2], s1b[3]));
            {
                uint32_t vb1[4];
                LDSM4T(vb1, vBase + 4 * ((vRow + grp * 16) * KP + vCol + 32));
                mma_f16(lacc0, a0, vb1[0], vb1[1]);
                mma_f16(lacc1, a1, vb1[0], vb1[1]);
            }
#pragma unroll
            for (int dp = 0; dp < 4; ++dp) {
                uint32_t vb[4];
                LDSM4T(vb, vBase + 4 * ((vRow + grp * 16) * KP + vCol + dp * 8));
                mma_f16(oacc0[2 * dp],     a0, vb[0], vb[1]);
                mma_f16(oacc0[2 * dp + 1], a0, vb[2], vb[3]);
                mma_f16(oacc1[2 * dp],     a1, vb[0], vb[1]);
                mma_f16(oacc1[2 * dp + 1], a1, vb[2], vb[3]);
            }
        }
    }

    const float l00 = __shfl_sync(0xffffffffu, lacc0[0], lane & 28);
    const float l01 = __shfl_sync(0xffffffffu, lacc0[2], lane & 28);
    const float l10 = __shfl_sync(0xffffffffu, lacc1[0], lane & 28);
    const float l11 = __shfl_sync(0xffffffffu, lacc1[2], lane & 28);

    const float i00 = 1.0f / l00, i01 = 1.0f / l01;
    const float i10 = 1.0f / l10, i11 = 1.0f / l11;
    __half* Ob = O + (size_t)b * T_ * HID + h * DH;
#pragma unroll
    for (int dt = 0; dt < 8; ++dt) {
        const int cl = dt * 8 + tq * 2;
        *(uint32_t*)(Ob + (size_t)(t0 + tb + g) * HID + cl) =
            pk16(oacc0[dt][0] * i00, oacc0[dt][1] * i00);
        *(uint32_t*)(Ob + (size_t)(t0 + tb + g + 8) * HID + cl) =
            pk16(oacc0[dt][2] * i01, oacc0[dt][3] * i01);
        *(uint32_t*)(Ob + (size_t)(t0 + tb + 16 + g) * HID + cl) =
            pk16(oacc1[dt][0] * i10, oacc1[dt][1] * i10);
        *(uint32_t*)(Ob + (size_t)(t0 + tb + 24 + g) * HID + cl) =
            pk16(oacc1[dt][2] * i11, oacc1[dt][3] * i11);
    }
}

// ---------------------------------------------------------------------------
extern "C" void kernel_launch(void* const* d_in, const int* in_sizes, int n_in,
                              void* d_out, int out_size)
{
    const float* tgt = (const float*)d_in[0];
    const float* src = (const float*)d_in[1];
    const float* Wq  = (const float*)d_in[2];
    const float* bq  = (const float*)d_in[3];
    const float* Wk  = (const float*)d_in[4];
    const float* bk  = (const float*)d_in[5];
    const float* Wv  = (const float*)d_in[6];
    const float* bv  = (const float*)d_in[7];
    const float* Wo  = (const float*)d_in[8];
    const float* bo  = (const float*)d_in[9];
    float* out = (float*)d_out;

    __half *t16, *s16, *wq, *wk, *wv, *wo, *q, *k, *v, *hb;
    cudaGetSymbolAddress((void**)&t16, g_t16);
    cudaGetSymbolAddress((void**)&s16, g_s16);
    cudaGetSymbolAddress((void**)&wq,  g_wq);
    cudaGetSymbolAddress((void**)&wk,  g_wk);
    cudaGetSymbolAddress((void**)&wv,  g_wv);
    cudaGetSymbolAddress((void**)&wo,  g_wo);
    cudaGetSymbolAddress((void**)&q,   g_q);
    cudaGetSymbolAddress((void**)&k,   g_k);
    cudaGetSymbolAddress((void**)&v,   g_v);
    cudaGetSymbolAddress((void**)&hb,  g_h);

    cudaFuncSetAttribute(gemm_qkv, cudaFuncAttributeMaxDynamicSharedMemorySize, GSMEM);
    cudaFuncSetAttribute(gemm_o,   cudaFuncAttributeMaxDynamicSharedMemorySize, GSMEM);
    cudaFuncSetAttribute(attn_fp16, cudaFuncAttributeMaxDynamicSharedMemorySize, ASMEM);

    // 1) convert everything to fp16 in one launch
    f2h_all<<<12288, 256>>>(tgt, src, Wq, Wk, Wv, Wo, t16, s16, wq, wk, wv, wo);

    // 2) fused QKV projections (256x128 tiles)
    dim3 gq(HID / 128, M_ / 256, 3);   // (8, 16, 3)
    gemm_qkv<<<gq, 256, GSMEM>>>(t16, s16, wq, wk, wv, bq, bk, bv, q, k, v);

    // 3) attention (128 threads, 4 warps x 32 rows)
    dim3 ga(T_ / 128, B_ * NH);        // (16, 32)
    attn_fp16<<<ga, 128, ASMEM>>>(q, k, v, hb);

    // 4) output projection
    dim3 gg(HID / 128, M_ / 256);      // (8, 16)
    gemm_o<<<gg, 256, GSMEM>>>(hb, wo, bo, out);
}

// round 14
// speedup vs baseline: 1.0286x; 1.0286x over previous
#include <cuda_runtime.h>
#include <cuda_fp16.h>
#include <cstdint>

#define B_  2
#define T_  2048
#define S_  2048
#define HID 1024
#define NH  16
#define DH  64
#define M_  (B_ * T_)   // 4096

// Scratch (static device globals — no allocation APIs)
__device__ __half g_t16[M_ * HID];
__device__ __half g_s16[M_ * HID];
__device__ __half g_wq[HID * HID];
__device__ __half g_wk[HID * HID];
__device__ __half g_wv[HID * HID];
__device__ __half g_wo[HID * HID];
__device__ __half g_q[M_ * HID];
__device__ __half g_k[M_ * HID];
__device__ __half g_v[M_ * HID];
__device__ __half g_h[M_ * HID];

// ---------------------------------------------------------------------------
// helpers
// ---------------------------------------------------------------------------
__device__ __forceinline__ uint32_t pk16(float x, float y) {
    uint32_t r;   // low half = x, high half = y
    asm("cvt.rn.f16x2.f32 %0, %1, %2;" : "=r"(r) : "f"(y), "f"(x));
    return r;
}
__device__ __forceinline__ uint32_t ex2h2(uint32_t x) {
    uint32_t r;   // 2^x on both fp16 halves, one MUFU op
    asm("ex2.approx.f16x2 %0, %1;" : "=r"(r) : "r"(x));
    return r;
}
__device__ __forceinline__ void mma_f16(float* c, const uint32_t* a,
                                        uint32_t b0, uint32_t b1) {
    asm volatile(
        "mma.sync.aligned.m16n8k16.row.col.f32.f16.f16.f32 "
        "{%0,%1,%2,%3}, {%4,%5,%6,%7}, {%8,%9}, {%0,%1,%2,%3};"
        : "+f"(c[0]), "+f"(c[1]), "+f"(c[2]), "+f"(c[3])
        : "r"(a[0]), "r"(a[1]), "r"(a[2]), "r"(a[3]), "r"(b0), "r"(b1));
}
__device__ __forceinline__ uint32_t smem_u32(const void* p) {
    uint32_t a;
    asm("{ .reg .u64 t; cvta.to.shared.u64 t, %1; cvt.u32.u64 %0, t; }"
        : "=r"(a) : "l"(p));
    return a;
}
#define LDSM4(r, a) \
    asm volatile("ldmatrix.sync.aligned.m8n8.x4.shared.b16 {%0,%1,%2,%3}, [%4];" \
        : "=r"((r)[0]), "=r"((r)[1]), "=r"((r)[2]), "=r"((r)[3]) : "r"(a))
#define LDSM4T(r, a) \
    asm volatile("ldmatrix.sync.aligned.m8n8.x4.trans.shared.b16 {%0,%1,%2,%3}, [%4];" \
        : "=r"((r)[0]), "=r"((r)[1]), "=r"((r)[2]), "=r"((r)[3]) : "r"(a))
#define CPA16(dst, src) \
    asm volatile("cp.async.cg.shared.global [%0], [%1], 16;" :: "r"(dst), "l"(src))
#define CPA_COMMIT() asm volatile("cp.async.commit_group;" ::: "memory")
#define CPA_WAIT1()  asm volatile("cp.async.wait_group 1;" ::: "memory")

// ---------------------------------------------------------------------------
// fused f32 -> f16 for all six tensors (one launch)
// ---------------------------------------------------------------------------
__global__ __launch_bounds__(256) void f2h_all(
    const float* __restrict__ tgt, const float* __restrict__ src,
    const float* __restrict__ Wq, const float* __restrict__ Wk,
    const float* __restrict__ Wv, const float* __restrict__ Wo,
    __half* t16, __half* s16, __half* wq, __half* wk, __half* wv, __half* wo)
{
    const int bid = blockIdx.x;
    const float* s;
    __half* d;
    int base;
    if      (bid < 4096)  { s = tgt; d = t16; base = bid; }
    else if (bid < 8192)  { s = src; d = s16; base = bid - 4096; }
    else if (bid < 9216)  { s = Wq;  d = wq;  base = bid - 8192; }
    else if (bid < 10240) { s = Wk;  d = wk;  base = bid - 9216; }
    else if (bid < 11264) { s = Wv;  d = wv;  base = bid - 10240; }
    else                  { s = Wo;  d = wo;  base = bid - 11264; }
    const int i = base * 256 + threadIdx.x;
    float4 v = ((const float4*)s)[i];
    ((uint2*)d)[i] = make_uint2(pk16(v.x, v.y), pk16(v.z, v.w));
}

// ---------------------------------------------------------------------------
// fp16 GEMM core (R10/R12 configuration — the measured best): 128x128 CTA
// tile, 8 warps, k-chunk 64, 3-stage cp.async, 1 sync/chunk, (256,2).
// ---------------------------------------------------------------------------
#define PA2 36
#define PB  68
#define GSMEM ((3 * 128 * PA2 + 3 * 64 * PB) * 4)   // 107520 B

__device__ __forceinline__ void gemm_core(
    const __half* __restrict__ A, const __half* __restrict__ W,
    const float* __restrict__ bias, void* __restrict__ Cout,
    int headMode, int halfOut, uint32_t* sm)
{
    uint32_t* sA = sm;
    uint32_t* sB = sm + 3 * 128 * PA2;

    const int tid = threadIdx.x;
    const int lane = tid & 31, wid = tid >> 5;
    const int g = lane >> 2, tq = lane & 3;
    const int wm = wid & 1, wn = wid >> 1;
    const int m0 = blockIdx.y * 128, n0 = blockIdx.x * 128;

    const uint32_t sAu = smem_u32(sA), sBu = smem_u32(sB);
    const uint32_t aRow = (uint32_t)(wm * 64 + (lane & 15));
    const uint32_t aCol = (uint32_t)((lane >> 4) * 4);
    const uint32_t bRow = (uint32_t)((lane & 7) + (lane & 8));
    const uint32_t bCol = (uint32_t)(wn * 16 + (lane >> 4) * 4);

    float acc[4][4][4];
#pragma unroll
    for (int i = 0; i < 4; i++)
#pragma unroll
        for (int j = 0; j < 4; j++)
#pragma unroll
            for (int u = 0; u < 4; u++) acc[i][j][u] = 0.0f;

    auto issue = [&](int c) {
        const int buf = c % 3;
#pragma unroll
        for (int i = 0; i < 4; ++i) {
            const int idx = i * 256 + tid;
            {
                const int row = idx >> 3, j = idx & 7;
                const uint32_t d = sAu + 4 * ((uint32_t)(buf * 128 + row) * PA2 + j * 4);
                CPA16(d, A + (size_t)(m0 + row) * HID + c * 64 + j * 8);
            }
            {
                const int k = idx >> 4, j = idx & 15;
                const int kg = c * 64 + k;
                const __half* src;
                if (headMode) {
                    const int n = n0 + j * 8;
                    src = W + (size_t)(n >> 6) * (HID * DH) + (size_t)kg * DH + (n & 63);
                } else {
                    src = W + (size_t)kg * HID + n0 + j * 8;
                }
                const uint32_t d = sBu + 4 * ((uint32_t)(buf * 64 + k) * PB + j * 4);
                CPA16(d, src);
            }
        }
        CPA_COMMIT();
    };

    issue(0);
    issue(1);

    for (int c = 0; c < 16; ++c) {
        CPA_WAIT1();
        __syncthreads();
        if (c + 2 < 16) issue(c + 2); else CPA_COMMIT();

        const int cur = c % 3;
        const uint32_t aBase = sAu + 4 * ((uint32_t)cur * 128 * PA2);
        const uint32_t bBase = sBu + 4 * ((uint32_t)cur * 64 * PB);
#pragma unroll
        for (int ks = 0; ks < 4; ++ks) {
            uint32_t af[4][4], bf[2][4];
#pragma unroll
            for (int mt = 0; mt < 4; ++mt)
                LDSM4(af[mt], aBase + 4 * ((aRow + mt * 16) * PA2 + aCol + ks * 8));
#pragma unroll
            for (int np = 0; np < 2; ++np)
                LDSM4T(bf[np], bBase + 4 * ((bRow + ks * 16) * PB + bCol + np * 8));
#pragma unroll
            for (int mt = 0; mt < 4; ++mt)
#pragma unroll
                for (int nt = 0; nt < 4; ++nt)
                    mma_f16(acc[mt][nt], af[mt], bf[nt >> 1][(nt & 1) * 2],
                            bf[nt >> 1][(nt & 1) * 2 + 1]);
        }
    }

#pragma unroll
    for (int mt = 0; mt < 4; ++mt) {
        const int r0 = m0 + wm * 64 + mt * 16 + g;
#pragma unroll
        for (int nt = 0; nt < 4; ++nt) {
            const int cl = n0 + wn * 32 + nt * 8 + tq * 2;
            const float b0v = bias[cl], b1v = bias[cl + 1];
            if (halfOut) {
                *(uint32_t*)((__half*)Cout + (size_t)r0 * HID + cl) =
                    pk16(acc[mt][nt][0] + b0v, acc[mt][nt][1] + b1v);
                *(uint32_t*)((__half*)Cout + (size_t)(r0 + 8) * HID + cl) =
                    pk16(acc[mt][nt][2] + b0v, acc[mt][nt][3] + b1v);
            } else {
                *(float2*)((float*)Cout + (size_t)r0 * HID + cl) =
                    make_float2(acc[mt][nt][0] + b0v, acc[mt][nt][1] + b1v);
                *(float2*)((float*)Cout + (size_t)(r0 + 8) * HID + cl) =
                    make_float2(acc[mt][nt][2] + b0v, acc[mt][nt][3] + b1v);
            }
        }
    }
}

__global__ __launch_bounds__(256, 2) void gemm_qkv(
    const __half* __restrict__ t16, const __half* __restrict__ s16,
    const __half* __restrict__ wq, const __half* __restrict__ wk,
    const __half* __restrict__ wv,
    const float* __restrict__ bq, const float* __restrict__ bk,
    const float* __restrict__ bv,
    __half* __restrict__ q, __half* __restrict__ k, __half* __restrict__ v)
{
    extern __shared__ __align__(16) uint32_t sm[];
    const __half* A;
    const __half* W;
    const float* bias;
    __half* C;
    if (blockIdx.z == 0)      { A = t16; W = wq; bias = bq; C = q; }
    else if (blockIdx.z == 1) { A = s16; W = wk; bias = bk; C = k; }
    else                      { A = s16; W = wv; bias = bv; C = v; }
    gemm_core(A, W, bias, C, 1, 1, sm);
}

__global__ __launch_bounds__(256, 2) void gemm_o(
    const __half* __restrict__ A, const __half* __restrict__ W,
    const float* __restrict__ bias, float* __restrict__ C)
{
    extern __shared__ __align__(16) uint32_t sm[];
    gemm_core(A, W, bias, C, 0, 0, sm);
}

// ---------------------------------------------------------------------------
// fp16 flash attention: 4 warps x 32 T-rows (two 16-row m-tiles), no online
// max, f16x2 exp. Row-sums l computed on the tensor pipe via a CONSTANT
// ones B-fragment (lanes 0-3 hold 0x3C003C00, others 0) — no smem pad
// column, no per-chunk ones-LDSM (saves 4 of 36 LDSM/warp-chunk).
// ---------------------------------------------------------------------------
#define KP 36
#define ASMEM (2 * 3 * 64 * KP * 4)   // 55296 B

__global__ __launch_bounds__(128, 3) void attn_fp16(
    const __half* __restrict__ Q, const __half* __restrict__ K,
    const __half* __restrict__ V, __half* __restrict__ O)
{
    extern __shared__ __align__(16) uint32_t smA[];
    uint32_t* sK = smA;
    uint32_t* sV = smA + 3 * 64 * KP;

    const int tid = threadIdx.x;
    const int lane = tid & 31, wid = tid >> 5;   // wid 0..3
    const int g = lane >> 2, tq = lane & 3;
    const int tb = wid * 32;                      // 32 rows per warp
    const int bh = blockIdx.y, b = bh >> 4, h = bh & 15;
    const int t0 = blockIdx.x * 128;

    const __half* Qb = Q + (size_t)b * T_ * HID + h * DH;
    const __half* Kb = K + (size_t)b * S_ * HID + h * DH;
    const __half* Vb = V + (size_t)b * S_ * HID + h * DH;

    const uint32_t sKu = smem_u32(sK), sVu = smem_u32(sV);
    const uint32_t kRow = (uint32_t)((lane & 7) + ((lane & 16) >> 1));
    const uint32_t kCol = (uint32_t)(((lane >> 3) & 1) * 4);
    const uint32_t vRow = (uint32_t)((lane & 7) + (lane & 8));
    const uint32_t vCol = (uint32_t)((lane >> 4) * 4);

    // constant ones B-fragment for the l-MMA (col 0 of virtual n8 tile = 1.0,
    // cols 1..7 = 0): n = lane>>2, value 1.0 for all k -> lanes 0-3 packed ones
    const uint32_t onesB = (lane < 4) ? 0x3C003C00u : 0u;

    // Q fragments for both m-tiles, pre-scaled by (1/8)*log2(e)
    const float QSC = 0.125f * 1.44269504f;
    uint32_t qh[4][8];   // [ks][mtile0: 0..3, mtile1: 4..7]
#pragma unroll
    for (int ks = 0; ks < 4; ++ks) {
        const int k = ks * 16 + tq * 2;
#pragma unroll
        for (int mt = 0; mt < 2; ++mt) {
            const size_t r0 = (size_t)(t0 + tb + mt * 16 + g) * HID;
            const size_t r1 = (size_t)(t0 + tb + mt * 16 + g + 8) * HID;
            const uint32_t u0 = *(const uint32_t*)(Qb + r0 + k);
            const uint32_t u1 = *(const uint32_t*)(Qb + r1 + k);
            const uint32_t u2 = *(const uint32_t*)(Qb + r0 + k + 8);
            const uint32_t u3 = *(const uint32_t*)(Qb + r1 + k + 8);
            float2 f0 = __half22float2(*(const __half2*)&u0);
            float2 f1 = __half22float2(*(const __half2*)&u1);
            float2 f2 = __half22float2(*(const __half2*)&u2);
            float2 f3 = __half22float2(*(const __half2*)&u3);
            qh[ks][mt * 4 + 0] = pk16(f0.x * QSC, f0.y * QSC);
            qh[ks][mt * 4 + 1] = pk16(f1.x * QSC, f1.y * QSC);
            qh[ks][mt * 4 + 2] = pk16(f2.x * QSC, f2.y * QSC);
            qh[ks][mt * 4 + 3] = pk16(f3.x * QSC, f3.y * QSC);
        }
    }

    auto issue = [&](int c) {
        const int buf = c % 3;
#pragma unroll
        for (int i = 0; i < 4; ++i) {
            const int idx = i * 128 + tid;
            const int row = idx >> 3, j = idx & 7;
            const uint32_t off = 4 * ((uint32_t)(buf * 64 + row) * KP + j * 4);
            CPA16(sKu + off, Kb + (size_t)(c * 64 + row) * HID + j * 8);
            CPA16(sVu + off, Vb + (size_t)(c * 64 + row) * HID + j * 8);
        }
        CPA_COMMIT();
    };

    float oacc0[8][4], oacc1[8][4];
#pragma unroll
    for (int dt = 0; dt < 8; ++dt)
#pragma unroll
        for (int u = 0; u < 4; ++u) { oacc0[dt][u] = 0.0f; oacc1[dt][u] = 0.0f; }
    float lacc0[4] = {0.f, 0.f, 0.f, 0.f};
    float lacc1[4] = {0.f, 0.f, 0.f, 0.f};

    issue(0);
    issue(1);

    const int NC = S_ / 64;   // 32
    for (int c = 0; c < NC; ++c) {
        CPA_WAIT1();
        __syncthreads();
        if (c + 2 < NC) issue(c + 2); else CPA_COMMIT();

        const int cur = c % 3;
        const uint32_t kBase = sKu + 4 * ((uint32_t)cur * 64 * KP);
        const uint32_t vBase = sVu + 4 * ((uint32_t)cur * 64 * KP);

#pragma unroll
        for (int grp = 0; grp < 4; ++grp) {
            float s0a[4] = {0.f, 0.f, 0.f, 0.f};
            float s0b[4] = {0.f, 0.f, 0.f, 0.f};
            float s1a[4] = {0.f, 0.f, 0.f, 0.f};
            float s1b[4] = {0.f, 0.f, 0.f, 0.f};
#pragma unroll
            for (int ks = 0; ks < 4; ++ks) {
                uint32_t kb[4];
                LDSM4(kb, kBase + 4 * ((kRow + grp * 16) * KP + kCol + ks * 8));
                mma_f16(s0a, &qh[ks][0], kb[0], kb[1]);
                mma_f16(s0b, &qh[ks][0], kb[2], kb[3]);
                mma_f16(s1a, &qh[ks][4], kb[0], kb[1]);
                mma_f16(s1b, &qh[ks][4], kb[2], kb[3]);
            }
            uint32_t a0[4], a1[4];
            a0[0] = ex2h2(pk16(s0a[0], s0a[1]));
            a0[1] = ex2h2(pk16(s0a[2], s0a[3]));
            a0[2] = ex2h2(pk16(s0b[0], s0b[1]));
            a0[3] = ex2h2(pk16(s0b[2], s0b[3]));
            a1[0] = ex2h2(pk16(s1a[0], s1a[1]));
            a1[1] = ex2h2(pk16(s1a[2], s1a[3]));
            a1[2] = ex2h2(pk16(s1b[0], s1b[1]));
            a1[3] = ex2h2(pk16(s1b[2], s1b[3]));
            // l += P @ ones — constant B fragment, zero smem traffic
            mma_f16(lacc0, a0, onesB, onesB);
            mma_f16(lacc1, a1, onesB, onesB);
            // O += P @ V
#pragma unroll
            for (int dp = 0; dp < 4; ++dp) {
                uint32_t vb[4];
                LDSM4T(vb, vBase + 4 * ((vRow + grp * 16) * KP + vCol + dp * 8));
                mma_f16(oacc0[2 * dp],     a0, vb[0], vb[1]);
                mma_f16(oacc0[2 * dp + 1], a0, vb[2], vb[3]);
                mma_f16(oacc1[2 * dp],     a1, vb[0], vb[1]);
                mma_f16(oacc1[2 * dp + 1], a1, vb[2], vb[3]);
            }
        }
    }

    // l sits in column 0 of the virtual ones-tile -> tq==0 lanes, c0/c2
    const float l00 = __shfl_sync(0xffffffffu, lacc0[0], lane & 28);
    const float l01 = __shfl_sync(0xffffffffu, lacc0[2], lane & 28);
    const float l10 = __shfl_sync(0xffffffffu, lacc1[0], lane & 28);
    const float l11 = __shfl_sync(0xffffffffu, lacc1[2], lane & 28);

    const float i00 = 1.0f / l00, i01 = 1.0f / l01;
    const float i10 = 1.0f / l10, i11 = 1.0f / l11;
    __half* Ob = O + (size_t)b * T_ * HID + h * DH;
#pragma unroll
    for (int dt = 0; dt < 8; ++dt) {
        const int cl = dt * 8 + tq * 2;
        *(uint32_t*)(Ob + (size_t)(t0 + tb + g) * HID + cl) =
            pk16(oacc0[dt][0] * i00, oacc0[dt][1] * i00);
        *(uint32_t*)(Ob + (size_t)(t0 + tb + g + 8) * HID + cl) =
            pk16(oacc0[dt][2] * i01, oacc0[dt][3] * i01);
        *(uint32_t*)(Ob + (size_t)(t0 + tb + 16 + g) * HID + cl) =
            pk16(oacc1[dt][0] * i10, oacc1[dt][1] * i10);
        *(uint32_t*)(Ob + (size_t)(t0 + tb + 24 + g) * HID + cl) =
            pk16(oacc1[dt][2] * i11, oacc1[dt][3] * i11);
    }
}

// ---------------------------------------------------------------------------
extern "C" void kernel_launch(void* const* d_in, const int* in_sizes, int n_in,
                              void* d_out, int out_size)
{
    const float* tgt = (const float*)d_in[0];
    const float* src = (const float*)d_in[1];
    const float* Wq  = (const float*)d_in[2];
    const float* bq  = (const float*)d_in[3];
    const float* Wk  = (const float*)d_in[4];
    const float* bk  = (const float*)d_in[5];
    const float* Wv  = (const float*)d_in[6];
    const float* bv  = (const float*)d_in[7];
    const float* Wo  = (const float*)d_in[8];
    const float* bo  = (const float*)d_in[9];
    float* out = (float*)d_out;

    __half *t16, *s16, *wq, *wk, *wv, *wo, *q, *k, *v, *hb;
    cudaGetSymbolAddress((void**)&t16, g_t16);
    cudaGetSymbolAddress((void**)&s16, g_s16);
    cudaGetSymbolAddress((void**)&wq,  g_wq);
    cudaGetSymbolAddress((void**)&wk,  g_wk);
    cudaGetSymbolAddress((void**)&wv,  g_wv);
    cudaGetSymbolAddress((void**)&wo,  g_wo);
    cudaGetSymbolAddress((void**)&q,   g_q);
    cudaGetSymbolAddress((void**)&k,   g_k);
    cudaGetSymbolAddress((void**)&v,   g_v);
    cudaGetSymbolAddress((void**)&hb,  g_h);

    cudaFuncSetAttribute(gemm_qkv, cudaFuncAttributeMaxDynamicSharedMemorySize, GSMEM);
    cudaFuncSetAttribute(gemm_o,   cudaFuncAttributeMaxDynamicSharedMemorySize, GSMEM);
    cudaFuncSetAttribute(attn_fp16, cudaFuncAttributeMaxDynamicSharedMemorySize, ASMEM);

    // 1) convert everything to fp16 in one launch
    f2h_all<<<12288, 256>>>(tgt, src, Wq, Wk, Wv, Wo, t16, s16, wq, wk, wv, wo);

    // 2) fused QKV projections (128x128 tiles, R10 config)
    dim3 gq(HID / 128, M_ / 128, 3);   // (8, 32, 3)
    gemm_qkv<<<gq, 256, GSMEM>>>(t16, s16, wq, wk, wv, bq, bk, bv, q, k, v);

    // 3) attention (128 threads, 4 warps x 32 rows)
    dim3 ga(T_ / 128, B_ * NH);        // (16, 32)
    attn_fp16<<<ga, 128, ASMEM>>>(q, k, v, hb);

    // 4) output projection
    dim3 gg(HID / 128, M_ / 128);      // (8, 32)
    gemm_o<<<gg, 256, GSMEM>>>(hb, wo, bo, out);
}